// round 6
// baseline (speedup 1.0000x reference)
#include <cuda_runtime.h>
#include <cuda_bf16.h>
#include <cstdint>
#include <math.h>

#define TSTEPS 512
#define BATCH  64
#define NIN    512
#define NH     1024
#define NBLK   128

// ============================ global scratch ================================
__device__ float g_X[(size_t)3 * TSTEPS * BATCH * NH];   // input projections
__device__ float g_h32[BATCH * NH];                      // h (fp32, plain)
// A-operand planes in mma fragment order: frag(kf,mf)=kf*4+mf -> uint4[frag*32+lane]
__device__ uint4 g_hhf[2][8192], g_hlf[2][8192];         // h split planes (parity)
__device__ uint4 g_rhhf[8192], g_rhlf[8192];             // r*h split planes
__device__ float g_cpart[64 * 64 * 16];                  // c-gemm low-K partials
__device__ int g_fh[64], g_frh[64], g_fcp[64];           // step flags

// ============================ helpers =======================================
__device__ __forceinline__ uint32_t bfpack(float x, float y) {
    __nv_bfloat162 t = __floats2bfloat162_rn(x, y);
    return *(uint32_t*)&t;
}
__device__ __forceinline__ void splitp(float x, float y, uint32_t& hi, uint32_t& lo) {
    float hx = __bfloat162float(__float2bfloat16(x));
    float hy = __bfloat162float(__float2bfloat16(y));
    hi = bfpack(hx, hy);
    lo = bfpack(x - hx, y - hy);
}
__device__ __forceinline__ void mma16816(float* c, const uint32_t* a, const uint32_t* b) {
    asm volatile("mma.sync.aligned.m16n8k16.row.col.f32.bf16.bf16.f32 "
        "{%0,%1,%2,%3},{%4,%5,%6,%7},{%8,%9},{%0,%1,%2,%3};"
        : "+f"(c[0]), "+f"(c[1]), "+f"(c[2]), "+f"(c[3])
        : "r"(a[0]), "r"(a[1]), "r"(a[2]), "r"(a[3]), "r"(b[0]), "r"(b[1]));
}
__device__ __forceinline__ int ld_acq(const int* p) {
    int v;
    asm volatile("ld.acquire.gpu.global.s32 %0, [%1];" : "=r"(v) : "l"(p) : "memory");
    return v;
}
__device__ __forceinline__ void st_rel(int* p, int v) {
    asm volatile("st.release.gpu.global.s32 [%0], %1;" :: "l"(p), "r"(v) : "memory");
}
__device__ __forceinline__ void warp_wait16(const int* flags, int target) {
    const int i = threadIdx.x & 15;
    if (__all_sync(0xFFFFFFFFu, ld_acq(flags + i) >= target)) return;
    while (!__all_sync(0xFFFFFFFFu, ld_acq(flags + i) >= target)) __nanosleep(20);
}
__device__ __forceinline__ void warp_wait8(const int* flags, int target) {
    const int i = threadIdx.x & 7;
    if (__all_sync(0xFFFFFFFFu, ld_acq(flags + i) >= target)) return;
    while (!__all_sync(0xFFFFFFFFu, ld_acq(flags + i) >= target)) __nanosleep(20);
}

// =================== init: reset flags each launch ==========================
__global__ void init_misc_kernel() {
    int i = threadIdx.x;
    if (i < 64) { g_fh[i] = -1; g_frh[i] = -1; g_fcp[i] = -1; }
}

// ======================= phase A: input projections =========================
#define PA_AH 0
#define PA_AL 32768
#define PA_WH 65536
#define PA_WL 98304
#define PA_SMEM 131072

__global__ void __launch_bounds__(256) input_proj_kernel(
    const float* __restrict__ input,
    const float* __restrict__ Wiz, const float* __restrict__ Wir,
    const float* __restrict__ Wih)
{
    extern __shared__ char sm[];
    uint4* Ah = (uint4*)(sm + PA_AH);
    uint4* Al = (uint4*)(sm + PA_AL);
    uint2* Wh = (uint2*)(sm + PA_WH);
    uint2* Wl = (uint2*)(sm + PA_WL);
    const int tid = threadIdx.x, wid = tid >> 5, lane = tid & 31;
    const int ntile = blockIdx.x % 24, mtile = blockIdx.x / 24;
    const int gate = ntile >> 3, n0g = (ntile & 7) * 128, m0 = mtile * 128;
    const float* W = (gate == 0) ? Wiz : ((gate == 1) ? Wir : Wih);
    const int mg = wid & 3, ng = wid >> 2;

    float c[2][8][4];
#pragma unroll
    for (int i = 0; i < 2; i++)
#pragma unroll
        for (int j = 0; j < 8; j++)
#pragma unroll
            for (int k = 0; k < 4; k++) c[i][j][k] = 0.0f;

    for (int ch = 0; ch < 4; ch++) {
        const int k0 = ch * 128;
        __syncthreads();
#pragma unroll
        for (int it = 0; it < 8; it++) {
            int idx = tid + (it << 8);
            int frag = idx >> 5, l = idx & 31;
            int kf = frag >> 3, mf = frag & 7;
            int r = l >> 2, c2 = (l & 3) * 2;
            const float* src = input + (size_t)(m0 + mf * 16 + r) * NIN + k0 + kf * 16 + c2;
            float2 p0 = *(const float2*)(src);
            float2 p1 = *(const float2*)(src + 8 * NIN);
            float2 p2 = *(const float2*)(src + 8);
            float2 p3 = *(const float2*)(src + 8 * NIN + 8);
            uint32_t h0, h1, h2, h3, lo0, lo1, lo2, lo3;
            splitp(p0.x, p0.y, h0, lo0); splitp(p1.x, p1.y, h1, lo1);
            splitp(p2.x, p2.y, h2, lo2); splitp(p3.x, p3.y, h3, lo3);
            Ah[frag * 32 + l] = make_uint4(h0, h1, h2, h3);
            Al[frag * 32 + l] = make_uint4(lo0, lo1, lo2, lo3);
        }
#pragma unroll
        for (int it = 0; it < 16; it++) {
            int idx = tid + (it << 8);
            int frag = idx >> 5, l = idx & 31;
            int kf = frag >> 4, nf = frag & 15;
            int n = nf * 8 + (l >> 2), k = kf * 16 + (l & 3) * 2;
            const float* src = W + (size_t)(n0g + n) * NIN + k0 + k;
            float2 q0 = *(const float2*)src;
            float2 q1 = *(const float2*)(src + 8);
            uint32_t h0, h1, lo0, lo1;
            splitp(q0.x, q0.y, h0, lo0); splitp(q1.x, q1.y, h1, lo1);
            Wh[frag * 32 + l] = make_uint2(h0, h1);
            Wl[frag * 32 + l] = make_uint2(lo0, lo1);
        }
        __syncthreads();
#pragma unroll 2
        for (int s = 0; s < 8; s++) {
            uint4 ah[2], al[2];
            uint2 bh[8], bl[8];
            ah[0] = Ah[(s * 8 + mg * 2 + 0) * 32 + lane];
            ah[1] = Ah[(s * 8 + mg * 2 + 1) * 32 + lane];
            al[0] = Al[(s * 8 + mg * 2 + 0) * 32 + lane];
            al[1] = Al[(s * 8 + mg * 2 + 1) * 32 + lane];
#pragma unroll
            for (int nf = 0; nf < 8; nf++) {
                bh[nf] = Wh[(s * 16 + ng * 8 + nf) * 32 + lane];
                bl[nf] = Wl[(s * 16 + ng * 8 + nf) * 32 + lane];
            }
#pragma unroll
            for (int mf = 0; mf < 2; mf++)
#pragma unroll
                for (int nf = 0; nf < 8; nf++) {
                    mma16816(c[mf][nf], &ah[mf].x, &bh[nf].x);
                    mma16816(c[mf][nf], &al[mf].x, &bh[nf].x);
                    mma16816(c[mf][nf], &ah[mf].x, &bl[nf].x);
                }
        }
    }
    const int r = lane >> 2, c2 = (lane & 3) * 2;
#pragma unroll
    for (int mf = 0; mf < 2; mf++)
#pragma unroll
        for (int nf = 0; nf < 8; nf++) {
            size_t row = (size_t)(m0 + (mg * 2 + mf) * 16 + r);
            size_t base = ((size_t)gate * TSTEPS * BATCH + row) * NH
                        + n0g + (ng * 8 + nf) * 8 + c2;
            *(float2*)(g_X + base) = make_float2(c[mf][nf][0], c[mf][nf][1]);
            *(float2*)(g_X + base + (size_t)8 * NH) = make_float2(c[mf][nf][2], c[mf][nf][3]);
        }
}

// ======================= phase B: persistent GRU ============================
// 128 blocks. 0-63 "zc": z-gate (16 cols) + c high-K half + h update.
// 64-127 "rc": r-gate (16 cols) + c low-K half (partials to paired zc block).
#define W1_H 0          // gate W hi (128 frags)   32768
#define W1_L 32768
#define W2_H 65536      // c-half W hi (64 frags)  16384
#define W2_L 81920
#define PB_SCR  98304   // float[4][64][20]        20480
#define PB_SBUF 118784  // float[64][20]            5120
#define PB_BIA  123904  // float[32]  (biaG | biaC)
#define PB_SLEN 124032  // int[64]
#define PB_SMEM 124416

// C[64 x 16] += A[64 x 16*KF*4] @ W^T, 3-term, depth-2 operand pipeline.
// Warps: mg = wid&1 (32 rows), kg = wid>>1 (KF kf-frags each).
template<int KF>
__device__ __forceinline__ void gemm_t(const uint4* __restrict__ Aph,
                                       const uint4* __restrict__ Apl,
                                       int akf0,
                                       const uint2* __restrict__ Wh,
                                       const uint2* __restrict__ Wl,
                                       float* __restrict__ scr,
                                       int wid, int lane)
{
    const int mg = wid & 1, kg = wid >> 1;
    const int kfl0 = kg * KF;
    float c[2][2][4];
#pragma unroll
    for (int i = 0; i < 2; i++)
#pragma unroll
        for (int j = 0; j < 2; j++)
#pragma unroll
            for (int k = 0; k < 4; k++) c[i][j][k] = 0.0f;

    uint4 ah[2][2], al[2][2];
    uint2 bh[2][2], bl[2][2];
    {
        int af = ((akf0 + kfl0) * 4 + mg * 2) * 32 + lane;
        ah[0][0] = Aph[af]; ah[0][1] = Aph[af + 32];
        al[0][0] = Apl[af]; al[0][1] = Apl[af + 32];
        int wf = (kfl0 * 2) * 32 + lane;
        bh[0][0] = Wh[wf]; bh[0][1] = Wh[wf + 32];
        bl[0][0] = Wl[wf]; bl[0][1] = Wl[wf + 32];
    }
#pragma unroll
    for (int s = 0; s < KF; s++) {
        const int cur = s & 1, nxt = cur ^ 1;
        if (s + 1 < KF) {
            int af = ((akf0 + kfl0 + s + 1) * 4 + mg * 2) * 32 + lane;
            ah[nxt][0] = Aph[af]; ah[nxt][1] = Aph[af + 32];
            al[nxt][0] = Apl[af]; al[nxt][1] = Apl[af + 32];
            int wf = ((kfl0 + s + 1) * 2) * 32 + lane;
            bh[nxt][0] = Wh[wf]; bh[nxt][1] = Wh[wf + 32];
            bl[nxt][0] = Wl[wf]; bl[nxt][1] = Wl[wf + 32];
        }
#pragma unroll
        for (int mf = 0; mf < 2; mf++)
#pragma unroll
            for (int nf = 0; nf < 2; nf++) {
                mma16816(c[mf][nf], &ah[cur][mf].x, &bh[cur][nf].x);
                mma16816(c[mf][nf], &al[cur][mf].x, &bh[cur][nf].x);
                mma16816(c[mf][nf], &ah[cur][mf].x, &bl[cur][nf].x);
            }
    }
    const int r = lane >> 2, c2 = (lane & 3) * 2;
#pragma unroll
    for (int mf = 0; mf < 2; mf++)
#pragma unroll
        for (int nf = 0; nf < 2; nf++) {
            float* p = scr + (kg * 64 + mg * 32 + mf * 16 + r) * 20 + nf * 8 + c2;
            *(float2*)p = make_float2(c[mf][nf][0], c[mf][nf][1]);
            *(float2*)(p + 8 * 20) = make_float2(c[mf][nf][2], c[mf][nf][3]);
        }
}

// reduce 4 K-partials + x (+bias added by caller if wanted via bia!=null path)
__device__ __forceinline__ void reduce4(const float* __restrict__ scr,
                                        int m, int nq, float* pre)
{
#pragma unroll
    for (int kg = 0; kg < 4; kg++) {
        float4 a = *(const float4*)(scr + kg * 1280 + m * 20 + nq);
        pre[0] += a.x; pre[1] += a.y; pre[2] += a.z; pre[3] += a.w;
    }
}

// pack sbuf[64][20] (16 cols of values) into A-frag planes at kf = jkf
__device__ __forceinline__ void pack16(const float* __restrict__ sbuf,
                                       uint4* __restrict__ dsth,
                                       uint4* __restrict__ dstl,
                                       int jkf, int wid, int lane)
{
    if (wid < 4) {
        const int mf = wid;
        const int r = lane >> 2, c2 = (lane & 3) * 2;
        const float* p = sbuf + (mf * 16 + r) * 20 + c2;
        uint32_t h0, h1, h2, h3, l0, l1, l2, l3;
        splitp(p[0], p[1], h0, l0);
        splitp(p[160], p[161], h1, l1);
        splitp(p[8], p[9], h2, l2);
        splitp(p[168], p[169], h3, l3);
        const int fi = (jkf * 4 + mf) * 32 + lane;
        dsth[fi] = make_uint4(h0, h1, h2, h3);
        dstl[fi] = make_uint4(l0, l1, l2, l3);
    }
}

__global__ void __launch_bounds__(256, 1) gru_step_kernel(
    const float* __restrict__ h0in,
    const float* __restrict__ Whz, const float* __restrict__ Whr,
    const float* __restrict__ Whh,
    const float* __restrict__ Whz_b, const float* __restrict__ Whr_b,
    const float* __restrict__ Whh_b,
    const float* __restrict__ Wiz_b, const float* __restrict__ Wir_b,
    const float* __restrict__ Wih_b,
    const void* __restrict__ lengths,
    float* __restrict__ out, int write_last)
{
    extern __shared__ char sm[];
    uint2* W1h = (uint2*)(sm + W1_H);
    uint2* W1l = (uint2*)(sm + W1_L);
    uint2* W2h = (uint2*)(sm + W2_H);
    uint2* W2l = (uint2*)(sm + W2_L);
    float* scr = (float*)(sm + PB_SCR);
    float* sbuf = (float*)(sm + PB_SBUF);
    float* bia = (float*)(sm + PB_BIA);     // [0:16) gate, [16:32) cand
    int* slen = (int*)(sm + PB_SLEN);

    const int tid = threadIdx.x, wid = tid >> 5, lane = tid & 31;
    const int b = blockIdx.x;
    const int is_zc = (b < 64);
    const int j = b & 63;
    const int gn0 = j * 16;
    const int kgw = wid >> 1;

    const float* Wgate = is_zc ? Whz : Whr;
    const float* bgh   = is_zc ? Whz_b : Whr_b;
    const float* bgi   = is_zc ? Wiz_b : Wir_b;
    const int koff = is_zc ? 512 : 0;   // c-half K offset

    // ---- pack gate W slice (16 cols x K1024) : 128 frags ----
#pragma unroll 4
    for (int it = 0; it < 16; it++) {
        int idx = tid + (it << 8);
        int frag = idx >> 5, l = idx & 31;
        int kf = frag >> 1, nf = frag & 1;
        int n = nf * 8 + (l >> 2), k = kf * 16 + (l & 3) * 2;
        const float* src = Wgate + (size_t)(gn0 + n) * NH + k;
        float2 q0 = *(const float2*)src;
        float2 q1 = *(const float2*)(src + 8);
        uint32_t h0, h1, lo0, lo1;
        splitp(q0.x, q0.y, h0, lo0); splitp(q1.x, q1.y, h1, lo1);
        W1h[frag * 32 + l] = make_uint2(h0, h1);
        W1l[frag * 32 + l] = make_uint2(lo0, lo1);
    }
    // ---- pack c-half W slice (16 cols x K512) : 64 frags ----
#pragma unroll 4
    for (int it = 0; it < 8; it++) {
        int idx = tid + (it << 8);
        int frag = idx >> 5, l = idx & 31;
        int kf = frag >> 1, nf = frag & 1;
        int n = nf * 8 + (l >> 2), k = koff + kf * 16 + (l & 3) * 2;
        const float* src = Whh + (size_t)(gn0 + n) * NH + k;
        float2 q0 = *(const float2*)src;
        float2 q1 = *(const float2*)(src + 8);
        uint32_t h0, h1, lo0, lo1;
        splitp(q0.x, q0.y, h0, lo0); splitp(q1.x, q1.y, h1, lo1);
        W2h[frag * 32 + l] = make_uint2(h0, h1);
        W2l[frag * 32 + l] = make_uint2(lo0, lo1);
    }
    if (tid < 16) {
        bia[tid] = bgh[gn0 + tid] + bgi[gn0 + tid];
        bia[16 + tid] = Whh_b[gn0 + tid] + Wih_b[gn0 + tid];
    }
    {   // lengths dtype auto-detect (int64 -> high word of elem0 is 0)
        const int* L32 = (const int*)lengths;
        int is64 = (L32[1] == 0);
        if (tid < BATCH)
            slen[tid] = is64 ? (int)((const long long*)lengths)[tid] : L32[tid];
    }

    const int m = tid >> 2, nq = (tid & 3) * 4;
    float hreg[4];

    if (is_zc) {
        // init h: registers + plain fp32 + frag planes parity 0
        const float* src = h0in + (size_t)m * NH + gn0 + nq;
        float4 v = *(const float4*)src;
        hreg[0] = v.x; hreg[1] = v.y; hreg[2] = v.z; hreg[3] = v.w;
        *(float4*)(g_h32 + (size_t)m * NH + gn0 + nq) = v;
        *(float4*)(sbuf + m * 20 + nq) = v;
        __syncthreads();
        pack16(sbuf, g_hhf[0], g_hlf[0], j, wid, lane);
        __syncthreads();
        if (tid == 0) { __threadfence(); st_rel(&g_fh[j], 0); }
    } else {
        __syncthreads();
    }

    const int sl = slen[m];
    const size_t GATE = (size_t)TSTEPS * BATCH * NH;
    const size_t xrow = (size_t)m * NH + gn0 + nq;

    if (is_zc) {
        const float* Xz = g_X + xrow;               // gate 0
        const float* Xh = g_X + 2 * GATE + xrow;    // gate 2
        float* cpart = g_cpart + j * 1024 + m * 16 + nq;
        for (int t = 0; t < TSTEPS; t++) {
            float4 xz = *(const float4*)(Xz + (size_t)t * BATCH * NH);
            float4 xh = *(const float4*)(Xh + (size_t)t * BATCH * NH);
            // ---- z gemm ----
            warp_wait16(g_fh + kgw * 16, t);
            gemm_t<16>(g_hhf[t & 1], g_hlf[t & 1], 0, W1h, W1l, scr, wid, lane);
            __syncthreads();
            float zv[4] = {xz.x + bia[nq], xz.y + bia[nq + 1],
                           xz.z + bia[nq + 2], xz.w + bia[nq + 3]};
            reduce4(scr, m, nq, zv);
#pragma unroll
            for (int jj = 0; jj < 4; jj++) zv[jj] = 1.0f / (1.0f + expf(-zv[jj]));
            __syncthreads();     // scr consumed; safe to overwrite
            // ---- c gemm, high K half ----
            warp_wait8(g_frh + 32 + kgw * 8, t + 1);
            gemm_t<8>(g_rhhf, g_rhlf, 32, W2h, W2l, scr, wid, lane);
            __syncthreads();
            // ---- merge with partner's low-K partial, finish step ----
            while (ld_acq(&g_fcp[j]) < t + 1) __nanosleep(20);
            float4 cp = *(const float4*)cpart;
            float pre[4] = {xh.x + bia[16 + nq] + cp.x, xh.y + bia[16 + nq + 1] + cp.y,
                            xh.z + bia[16 + nq + 2] + cp.z, xh.w + bia[16 + nq + 3] + cp.w};
            reduce4(scr, m, nq, pre);
            float hn[4];
#pragma unroll
            for (int jj = 0; jj < 4; jj++) {
                float hc = tanhf(pre[jj]);
                float v = (1.0f - zv[jj]) * hreg[jj] + zv[jj] * hc;
                if (t >= sl) v = hreg[jj];
                hreg[jj] = v;
                hn[jj] = v;
            }
            float4 hv = make_float4(hn[0], hn[1], hn[2], hn[3]);
            *(float4*)(g_h32 + (size_t)m * NH + gn0 + nq) = hv;
            *(float4*)(out + (size_t)t * BATCH * NH + xrow) = hv;
            *(float4*)(sbuf + m * 20 + nq) = hv;
            __syncthreads();
            pack16(sbuf, g_hhf[(t + 1) & 1], g_hlf[(t + 1) & 1], j, wid, lane);
            __syncthreads();
            if (tid == 0) { __threadfence(); st_rel(&g_fh[j], t + 1); }
        }
        if (write_last) {
            *(float4*)(out + (size_t)TSTEPS * BATCH * NH + xrow) =
                make_float4(hreg[0], hreg[1], hreg[2], hreg[3]);
        }
    } else {
        const float* Xr = g_X + GATE + xrow;        // gate 1
        float* cpart = g_cpart + j * 1024 + m * 16 + nq;
        for (int t = 0; t < TSTEPS; t++) {
            float4 xr = *(const float4*)(Xr + (size_t)t * BATCH * NH);
            // ---- r gemm ----
            warp_wait16(g_fh + kgw * 16, t);
            gemm_t<16>(g_hhf[t & 1], g_hlf[t & 1], 0, W1h, W1l, scr, wid, lane);
            __syncthreads();
            float pre[4] = {xr.x + bia[nq], xr.y + bia[nq + 1],
                            xr.z + bia[nq + 2], xr.w + bia[nq + 3]};
            reduce4(scr, m, nq, pre);
            float4 hp = *(const float4*)(g_h32 + (size_t)m * NH + gn0 + nq);
            float hv[4] = {hp.x, hp.y, hp.z, hp.w};
            float rh[4];
#pragma unroll
            for (int jj = 0; jj < 4; jj++) {
                float s = 1.0f / (1.0f + expf(-pre[jj]));
                rh[jj] = s * hv[jj];
            }
            *(float4*)(sbuf + m * 20 + nq) = make_float4(rh[0], rh[1], rh[2], rh[3]);
            __syncthreads();
            pack16(sbuf, g_rhhf, g_rhlf, j, wid, lane);
            __syncthreads();
            if (tid == 0) { __threadfence(); st_rel(&g_frh[j], t + 1); }
            // ---- c gemm, low K half ----
            warp_wait8(g_frh + kgw * 8, t + 1);
            gemm_t<8>(g_rhhf, g_rhlf, 0, W2h, W2l, scr, wid, lane);
            __syncthreads();
            float part[4] = {0.0f, 0.0f, 0.0f, 0.0f};
            reduce4(scr, m, nq, part);
            *(float4*)cpart = make_float4(part[0], part[1], part[2], part[3]);
            __syncthreads();
            if (tid == 0) { __threadfence(); st_rel(&g_fcp[j], t + 1); }
        }
    }
}

// ============================= launch =======================================
extern "C" void kernel_launch(void* const* d_in, const int* in_sizes, int n_in,
                              void* d_out, int out_size)
{
    const float* input = (const float*)d_in[0];
    const float* h0    = (const float*)d_in[1];
    const float* Wiz_w = (const float*)d_in[2];
    const float* Wiz_b = (const float*)d_in[3];
    const float* Wir_w = (const float*)d_in[4];
    const float* Wir_b = (const float*)d_in[5];
    const float* Wih_w = (const float*)d_in[6];
    const float* Wih_b = (const float*)d_in[7];
    const float* Whz_w = (const float*)d_in[8];
    const float* Whz_b = (const float*)d_in[9];
    const float* Whr_w = (const float*)d_in[10];
    const float* Whr_b = (const float*)d_in[11];
    const float* Whh_w = (const float*)d_in[12];
    const float* Whh_b = (const float*)d_in[13];
    const void*  lengths = d_in[14];

    cudaFuncSetAttribute(input_proj_kernel,
                         cudaFuncAttributeMaxDynamicSharedMemorySize, PA_SMEM);
    cudaFuncSetAttribute(gru_step_kernel,
                         cudaFuncAttributeMaxDynamicSharedMemorySize, PB_SMEM);

    init_misc_kernel<<<1, 64>>>();
    input_proj_kernel<<<256 * 24, 256, PA_SMEM>>>(input, Wiz_w, Wir_w, Wih_w);

    int write_last = (out_size >= TSTEPS * BATCH * NH + BATCH * NH) ? 1 : 0;
    gru_step_kernel<<<NBLK, 256, PB_SMEM>>>(
        h0, Whz_w, Whr_w, Whh_w, Whz_b, Whr_b, Whh_b,
        Wiz_b, Wir_b, Wih_b, lengths, (float*)d_out, write_last);
}

// round 7
// speedup vs baseline: 1.2361x; 1.2361x over previous
#include <cuda_runtime.h>
#include <cuda_bf16.h>
#include <cstdint>
#include <math.h>

#define TSTEPS 512
#define BATCH  64
#define NIN    512
#define NH     1024
#define NBLK   96

// ============================ global scratch ================================
__device__ float g_X[(size_t)3 * TSTEPS * BATCH * NH];   // input projections
__device__ float g_h32[BATCH * NH];                      // h (fp32, plain)
__device__ float g_z[BATCH * NH];                        // z gate (plain)
// A-operand planes in mma fragment order: frag(kf,mf) -> uint4[frag*32 + lane]
__device__ uint4 g_hhf[2][8192], g_hlf[2][8192];         // h split planes (parity)
__device__ uint4 g_rhhf[8192], g_rhlf[8192];             // r*h split planes
// producer-consumer flags (monotonic step counters, reset each launch)
__device__ int g_fh[32], g_fr[32], g_fz[32];

// ============================ helpers =======================================
__device__ __forceinline__ uint32_t bfpack(float x, float y) {
    __nv_bfloat162 t = __floats2bfloat162_rn(x, y);
    return *(uint32_t*)&t;
}
__device__ __forceinline__ void splitp(float x, float y, uint32_t& hi, uint32_t& lo) {
    float hx = __bfloat162float(__float2bfloat16(x));
    float hy = __bfloat162float(__float2bfloat16(y));
    hi = bfpack(hx, hy);
    lo = bfpack(x - hx, y - hy);
}
__device__ __forceinline__ void mma16816(float* c, const uint32_t* a, const uint32_t* b) {
    asm volatile("mma.sync.aligned.m16n8k16.row.col.f32.bf16.bf16.f32 "
        "{%0,%1,%2,%3},{%4,%5,%6,%7},{%8,%9},{%0,%1,%2,%3};"
        : "+f"(c[0]), "+f"(c[1]), "+f"(c[2]), "+f"(c[3])
        : "r"(a[0]), "r"(a[1]), "r"(a[2]), "r"(a[3]), "r"(b[0]), "r"(b[1]));
}
__device__ __forceinline__ int ld_acq(const int* p) {
    int v;
    asm volatile("ld.acquire.gpu.global.s32 %0, [%1];" : "=r"(v) : "l"(p) : "memory");
    return v;
}
__device__ __forceinline__ void st_rel(int* p, int v) {
    asm volatile("st.release.gpu.global.s32 [%0], %1;" :: "l"(p), "r"(v) : "memory");
}
// ONE warp (warp 0) polls all 32 producer flags; block released by syncthreads.
// Cuts L2 poll traffic ~2 orders of magnitude vs all-warp polling.
__device__ __forceinline__ void block_wait32(const int* flags, int target) {
    if (threadIdx.x < 32) {
        while (!__all_sync(0xFFFFFFFFu, ld_acq(flags + threadIdx.x) >= target))
            __nanosleep(60);
    }
    __syncthreads();
}

// =================== init: reset flags each launch ==========================
__global__ void init_misc_kernel() {
    int i = threadIdx.x;
    if (i < 32) { g_fh[i] = -1; g_fr[i] = -1; g_fz[i] = -1; }
}

// ======================= phase A: input projections =========================
#define PA_AH 0
#define PA_AL 32768
#define PA_WH 65536
#define PA_WL 98304
#define PA_SMEM 131072

__global__ void __launch_bounds__(256) input_proj_kernel(
    const float* __restrict__ input,
    const float* __restrict__ Wiz, const float* __restrict__ Wir,
    const float* __restrict__ Wih)
{
    extern __shared__ char sm[];
    uint4* Ah = (uint4*)(sm + PA_AH);
    uint4* Al = (uint4*)(sm + PA_AL);
    uint2* Wh = (uint2*)(sm + PA_WH);
    uint2* Wl = (uint2*)(sm + PA_WL);
    const int tid = threadIdx.x, wid = tid >> 5, lane = tid & 31;
    const int ntile = blockIdx.x % 24, mtile = blockIdx.x / 24;
    const int gate = ntile >> 3, n0g = (ntile & 7) * 128, m0 = mtile * 128;
    const float* W = (gate == 0) ? Wiz : ((gate == 1) ? Wir : Wih);
    const int mg = wid & 3, ng = wid >> 2;

    float c[2][8][4];
#pragma unroll
    for (int i = 0; i < 2; i++)
#pragma unroll
        for (int j = 0; j < 8; j++)
#pragma unroll
            for (int k = 0; k < 4; k++) c[i][j][k] = 0.0f;

    for (int ch = 0; ch < 4; ch++) {
        const int k0 = ch * 128;
        __syncthreads();
#pragma unroll
        for (int it = 0; it < 8; it++) {
            int idx = tid + (it << 8);
            int frag = idx >> 5, l = idx & 31;
            int kf = frag >> 3, mf = frag & 7;
            int r = l >> 2, c2 = (l & 3) * 2;
            const float* src = input + (size_t)(m0 + mf * 16 + r) * NIN + k0 + kf * 16 + c2;
            float2 p0 = *(const float2*)(src);
            float2 p1 = *(const float2*)(src + 8 * NIN);
            float2 p2 = *(const float2*)(src + 8);
            float2 p3 = *(const float2*)(src + 8 * NIN + 8);
            uint32_t h0, h1, h2, h3, lo0, lo1, lo2, lo3;
            splitp(p0.x, p0.y, h0, lo0); splitp(p1.x, p1.y, h1, lo1);
            splitp(p2.x, p2.y, h2, lo2); splitp(p3.x, p3.y, h3, lo3);
            Ah[frag * 32 + l] = make_uint4(h0, h1, h2, h3);
            Al[frag * 32 + l] = make_uint4(lo0, lo1, lo2, lo3);
        }
#pragma unroll
        for (int it = 0; it < 16; it++) {
            int idx = tid + (it << 8);
            int frag = idx >> 5, l = idx & 31;
            int kf = frag >> 4, nf = frag & 15;
            int n = nf * 8 + (l >> 2), k = kf * 16 + (l & 3) * 2;
            const float* src = W + (size_t)(n0g + n) * NIN + k0 + k;
            float2 q0 = *(const float2*)src;
            float2 q1 = *(const float2*)(src + 8);
            uint32_t h0, h1, lo0, lo1;
            splitp(q0.x, q0.y, h0, lo0); splitp(q1.x, q1.y, h1, lo1);
            Wh[frag * 32 + l] = make_uint2(h0, h1);
            Wl[frag * 32 + l] = make_uint2(lo0, lo1);
        }
        __syncthreads();
#pragma unroll 2
        for (int s = 0; s < 8; s++) {
            uint4 ah[2], al[2];
            uint2 bh[8], bl[8];
            ah[0] = Ah[(s * 8 + mg * 2 + 0) * 32 + lane];
            ah[1] = Ah[(s * 8 + mg * 2 + 1) * 32 + lane];
            al[0] = Al[(s * 8 + mg * 2 + 0) * 32 + lane];
            al[1] = Al[(s * 8 + mg * 2 + 1) * 32 + lane];
#pragma unroll
            for (int nf = 0; nf < 8; nf++) {
                bh[nf] = Wh[(s * 16 + ng * 8 + nf) * 32 + lane];
                bl[nf] = Wl[(s * 16 + ng * 8 + nf) * 32 + lane];
            }
#pragma unroll
            for (int mf = 0; mf < 2; mf++)
#pragma unroll
                for (int nf = 0; nf < 8; nf++) {
                    mma16816(c[mf][nf], &ah[mf].x, &bh[nf].x);
                    mma16816(c[mf][nf], &al[mf].x, &bh[nf].x);
                    mma16816(c[mf][nf], &ah[mf].x, &bl[nf].x);
                }
        }
    }
    const int r = lane >> 2, c2 = (lane & 3) * 2;
#pragma unroll
    for (int mf = 0; mf < 2; mf++)
#pragma unroll
        for (int nf = 0; nf < 8; nf++) {
            size_t row = (size_t)(m0 + (mg * 2 + mf) * 16 + r);
            size_t base = ((size_t)gate * TSTEPS * BATCH + row) * NH
                        + n0g + (ng * 8 + nf) * 8 + c2;
            *(float2*)(g_X + base) = make_float2(c[mf][nf][0], c[mf][nf][1]);
            *(float2*)(g_X + base + (size_t)8 * NH) = make_float2(c[mf][nf][2], c[mf][nf][3]);
        }
}

// ======================= phase B: persistent GRU ============================
#define PBW_H   0
#define PBW_L   65536
#define PB_SCR  131072                  // float[4][64][36] partials
#define PB_SBUF 167936                  // float[64][36]
#define PB_BIA  177152                  // float[32]
#define PB_SLEN 177280                  // int[64]
#define PB_SMEM 177664

// C[64x32] = A[64x1024] @ Wslice^T, 3-term, depth-2 operand pipeline.
__device__ __forceinline__ void gemm_stage(const uint4* __restrict__ Aph,
                                           const uint4* __restrict__ Apl,
                                           const uint2* __restrict__ Wh,
                                           const uint2* __restrict__ Wl,
                                           float* __restrict__ scr,
                                           int wid, int lane)
{
    const int mg = wid & 1, kg = wid >> 1;
    const int kf0 = kg * 16;
    float c[2][4][4];
#pragma unroll
    for (int i = 0; i < 2; i++)
#pragma unroll
        for (int j = 0; j < 4; j++)
#pragma unroll
            for (int k = 0; k < 4; k++) c[i][j][k] = 0.0f;

    uint4 ah[2][2], al[2][2];
    uint2 bh[2][4], bl[2][4];
    {
        int base = (kf0 * 4 + mg * 2) * 32 + lane;
        ah[0][0] = Aph[base]; ah[0][1] = Aph[base + 32];
        al[0][0] = Apl[base]; al[0][1] = Apl[base + 32];
        int wb = (kf0 * 4) * 32 + lane;
#pragma unroll
        for (int nf = 0; nf < 4; nf++) { bh[0][nf] = Wh[wb + nf * 32]; bl[0][nf] = Wl[wb + nf * 32]; }
    }
#pragma unroll
    for (int s = 0; s < 16; s++) {
        const int cur = s & 1, nxt = cur ^ 1;
        if (s < 15) {
            int kf = kf0 + s + 1;
            int base = (kf * 4 + mg * 2) * 32 + lane;
            ah[nxt][0] = Aph[base]; ah[nxt][1] = Aph[base + 32];
            al[nxt][0] = Apl[base]; al[nxt][1] = Apl[base + 32];
            int wb = (kf * 4) * 32 + lane;
#pragma unroll
            for (int nf = 0; nf < 4; nf++) { bh[nxt][nf] = Wh[wb + nf * 32]; bl[nxt][nf] = Wl[wb + nf * 32]; }
        }
#pragma unroll
        for (int mf = 0; mf < 2; mf++)
#pragma unroll
            for (int nf = 0; nf < 4; nf++) {
                mma16816(c[mf][nf], &ah[cur][mf].x, &bh[cur][nf].x);
                mma16816(c[mf][nf], &al[cur][mf].x, &bh[cur][nf].x);
                mma16816(c[mf][nf], &ah[cur][mf].x, &bl[cur][nf].x);
            }
    }
    const int r = lane >> 2, c2 = (lane & 3) * 2;
#pragma unroll
    for (int mf = 0; mf < 2; mf++)
#pragma unroll
        for (int nf = 0; nf < 4; nf++) {
            float* p = scr + ((kg * 64 + mg * 32 + mf * 16 + r) * 36 + nf * 8 + c2);
            *(float2*)p = make_float2(c[mf][nf][0], c[mf][nf][1]);
            *(float2*)(p + 8 * 36) = make_float2(c[mf][nf][2], c[mf][nf][3]);
        }
}

// pack sbuf[64][36] (fp32 values for this block's 32 cols) into A-frag planes
__device__ __forceinline__ void pack_planes(const float* __restrict__ sbuf,
                                            uint4* __restrict__ dsth,
                                            uint4* __restrict__ dstl,
                                            int kfbase, int tid)
{
    const int f = tid >> 5, l = tid & 31;
    const int mf = f & 3, kfo = f >> 2;
    const int r = l >> 2, c2 = (l & 3) * 2;
    const float* p = sbuf + (mf * 16 + r) * 36 + kfo * 16 + c2;
    uint32_t h0, h1, h2, h3, lo0, lo1, lo2, lo3;
    splitp(p[0], p[1], h0, lo0);
    splitp(p[8 * 36], p[8 * 36 + 1], h1, lo1);
    splitp(p[8], p[9], h2, lo2);
    splitp(p[8 * 36 + 8], p[8 * 36 + 9], h3, lo3);
    const int frag = (kfbase + kfo) * 4 + mf;
    dsth[frag * 32 + l] = make_uint4(h0, h1, h2, h3);
    dstl[frag * 32 + l] = make_uint4(lo0, lo1, lo2, lo3);
}

// reduce 4 K-partials + X + bias into pre[8]
__device__ __forceinline__ void reduce_pre(const float* __restrict__ scr,
                                           const float* __restrict__ bia,
                                           const float4 x0, const float4 x1,
                                           int m, int nq, float* pre)
{
    pre[0] = x0.x; pre[1] = x0.y; pre[2] = x0.z; pre[3] = x0.w;
    pre[4] = x1.x; pre[5] = x1.y; pre[6] = x1.z; pre[7] = x1.w;
#pragma unroll
    for (int kg = 0; kg < 4; kg++) {
        const float* p = scr + ((kg * 64 + m) * 36 + nq);
        float4 a = *(const float4*)p;
        float4 bb = *(const float4*)(p + 4);
        pre[0] += a.x; pre[1] += a.y; pre[2] += a.z; pre[3] += a.w;
        pre[4] += bb.x; pre[5] += bb.y; pre[6] += bb.z; pre[7] += bb.w;
    }
#pragma unroll
    for (int j = 0; j < 8; j++) pre[j] += bia[nq + j];
}

__global__ void __launch_bounds__(256, 1) gru_step_kernel(
    const float* __restrict__ h0in,
    const float* __restrict__ Whz, const float* __restrict__ Whr,
    const float* __restrict__ Whh,
    const float* __restrict__ Whz_b, const float* __restrict__ Whr_b,
    const float* __restrict__ Whh_b,
    const float* __restrict__ Wiz_b, const float* __restrict__ Wir_b,
    const float* __restrict__ Wih_b,
    const void* __restrict__ lengths,
    float* __restrict__ out, int write_last)
{
    extern __shared__ char sm[];
    uint2* Wh = (uint2*)(sm + PBW_H);
    uint2* Wl = (uint2*)(sm + PBW_L);
    float* scr = (float*)(sm + PB_SCR);
    float* sbuf = (float*)(sm + PB_SBUF);
    float* bia = (float*)(sm + PB_BIA);
    int* slen = (int*)(sm + PB_SLEN);

    const int tid = threadIdx.x, wid = tid >> 5, lane = tid & 31;
    const int b = blockIdx.x;
    int role, j;
    const float *W, *bh, *bi;
    if (b < 32)      { role = 0; j = b;      W = Whz; bh = Whz_b; bi = Wiz_b; }
    else if (b < 64) { role = 1; j = b - 32; W = Whr; bh = Whr_b; bi = Wir_b; }
    else             { role = 2; j = b - 64; W = Whh; bh = Whh_b; bi = Wih_b; }
    const int gn0 = j * 32;

    // pack W slice into B-frag-order split planes
#pragma unroll 4
    for (int it = 0; it < 32; it++) {
        int idx = tid + (it << 8);
        int frag = idx >> 5, l = idx & 31;
        int kf = frag >> 2, nf = frag & 3;
        int n = nf * 8 + (l >> 2), k = kf * 16 + (l & 3) * 2;
        const float* src = W + (size_t)(gn0 + n) * NH + k;
        float2 q0 = *(const float2*)src;
        float2 q1 = *(const float2*)(src + 8);
        uint32_t h0, h1, lo0, lo1;
        splitp(q0.x, q0.y, h0, lo0); splitp(q1.x, q1.y, h1, lo1);
        Wh[frag * 32 + l] = make_uint2(h0, h1);
        Wl[frag * 32 + l] = make_uint2(lo0, lo1);
    }
    if (tid < 32) bia[tid] = bh[gn0 + tid] + bi[gn0 + tid];
    {   // lengths dtype auto-detect (int64 -> high word of elem0 is 0)
        const int* L32 = (const int*)lengths;
        int is64 = (L32[1] == 0);
        if (tid < BATCH)
            slen[tid] = is64 ? (int)((const long long*)lengths)[tid] : L32[tid];
    }

    const int m = tid >> 2, nq = (tid & 3) * 8;
    float hreg[8];

    if (role == 2) {
        // init h: registers + plain fp32 + frag-order planes parity 0
        const float* src = h0in + (size_t)m * NH + gn0 + nq;
        float4 v0 = *(const float4*)src;
        float4 v1 = *(const float4*)(src + 4);
        hreg[0] = v0.x; hreg[1] = v0.y; hreg[2] = v0.z; hreg[3] = v0.w;
        hreg[4] = v1.x; hreg[5] = v1.y; hreg[6] = v1.z; hreg[7] = v1.w;
        *(float4*)(g_h32 + (size_t)m * NH + gn0 + nq) = v0;
        *(float4*)(g_h32 + (size_t)m * NH + gn0 + nq + 4) = v1;
        {
            const int f = tid >> 5, l = tid & 31;
            const int mf = f & 3, kfo = f >> 2;
            const int r = l >> 2, c2 = (l & 3) * 2;
            const float* p = h0in + (size_t)(mf * 16 + r) * NH + gn0 + kfo * 16 + c2;
            uint32_t h0, h1, h2, h3, lo0, lo1, lo2, lo3;
            splitp(p[0], p[1], h0, lo0);
            splitp(p[8 * NH], p[8 * NH + 1], h1, lo1);
            splitp(p[8], p[9], h2, lo2);
            splitp(p[8 * NH + 8], p[8 * NH + 9], h3, lo3);
            const int frag = (j * 2 + kfo) * 4 + mf;
            g_hhf[0][frag * 32 + l] = make_uint4(h0, h1, h2, h3);
            g_hlf[0][frag * 32 + l] = make_uint4(lo0, lo1, lo2, lo3);
        }
        __syncthreads();
        if (tid == 0) { __threadfence(); st_rel(&g_fh[j], 0); }   // h(0) published
    } else {
        __syncthreads();
    }

    const int sl = slen[m];

    if (role == 0) {
        // -------- z-gate producer --------
        const float* Xbase = g_X + ((size_t)0 * TSTEPS * BATCH + (size_t)m) * NH + gn0 + nq;
        for (int t = 0; t < TSTEPS; t++) {
            const float* Xt = Xbase + (size_t)t * BATCH * NH;
            float4 x0 = *(const float4*)Xt;
            float4 x1 = *(const float4*)(Xt + 4);
            block_wait32(g_fh, t);
            gemm_stage(g_hhf[t & 1], g_hlf[t & 1], Wh, Wl, scr, wid, lane);
            __syncthreads();
            float pre[8];
            reduce_pre(scr, bia, x0, x1, m, nq, pre);
            float zv[8];
#pragma unroll
            for (int jj = 0; jj < 8; jj++) zv[jj] = 1.0f / (1.0f + expf(-pre[jj]));
            float* dst = g_z + (size_t)m * NH + gn0 + nq;
            *(float4*)dst = make_float4(zv[0], zv[1], zv[2], zv[3]);
            *(float4*)(dst + 4) = make_float4(zv[4], zv[5], zv[6], zv[7]);
            __syncthreads();
            if (tid == 0) { __threadfence(); st_rel(&g_fz[j], t + 1); }
        }
    } else if (role == 1) {
        // -------- r-gate producer (publishes r*h planes) --------
        const float* Xbase = g_X + ((size_t)1 * TSTEPS * BATCH + (size_t)m) * NH + gn0 + nq;
        for (int t = 0; t < TSTEPS; t++) {
            const float* Xt = Xbase + (size_t)t * BATCH * NH;
            float4 x0 = *(const float4*)Xt;
            float4 x1 = *(const float4*)(Xt + 4);
            block_wait32(g_fh, t);
            gemm_stage(g_hhf[t & 1], g_hlf[t & 1], Wh, Wl, scr, wid, lane);
            __syncthreads();
            float pre[8];
            reduce_pre(scr, bia, x0, x1, m, nq, pre);
            const float* hp = g_h32 + (size_t)m * NH + gn0 + nq;
#pragma unroll
            for (int jj = 0; jj < 8; jj++) {
                float s = 1.0f / (1.0f + expf(-pre[jj]));
                sbuf[m * 36 + nq + jj] = s * hp[jj];
            }
            __syncthreads();
            pack_planes(sbuf, g_rhhf, g_rhlf, j * 2, tid);
            __syncthreads();
            if (tid == 0) { __threadfence(); st_rel(&g_fr[j], t + 1); }
        }
    } else {
        // -------- candidate + update --------
        const float* Xbase = g_X + ((size_t)2 * TSTEPS * BATCH + (size_t)m) * NH + gn0 + nq;
        for (int t = 0; t < TSTEPS; t++) {
            const float* Xt = Xbase + (size_t)t * BATCH * NH;
            float4 x0 = *(const float4*)Xt;
            float4 x1 = *(const float4*)(Xt + 4);
            block_wait32(g_fr, t + 1);
            gemm_stage(g_rhhf, g_rhlf, Wh, Wl, scr, wid, lane);
            // single-thread z-wait; the syncthreads below orders all threads
            if (tid == 0) {
                while (ld_acq(&g_fz[j]) < t + 1) __nanosleep(60);
            }
            __syncthreads();
            float pre[8];
            reduce_pre(scr, bia, x0, x1, m, nq, pre);
            const float* zp = g_z + (size_t)m * NH + gn0 + nq;
            float4 z0 = *(const float4*)zp;
            float4 z1 = *(const float4*)(zp + 4);
            float zv[8] = {z0.x, z0.y, z0.z, z0.w, z1.x, z1.y, z1.z, z1.w};
            float hn[8];
#pragma unroll
            for (int jj = 0; jj < 8; jj++) {
                float hc = tanhf(pre[jj]);
                float v = (1.0f - zv[jj]) * hreg[jj] + zv[jj] * hc;
                if (t >= sl) v = hreg[jj];
                hreg[jj] = v;
                hn[jj] = v;
                sbuf[m * 36 + nq + jj] = v;
            }
            float* hp = g_h32 + (size_t)m * NH + gn0 + nq;
            *(float4*)hp = make_float4(hn[0], hn[1], hn[2], hn[3]);
            *(float4*)(hp + 4) = make_float4(hn[4], hn[5], hn[6], hn[7]);
            float* op = out + (size_t)t * BATCH * NH + (size_t)m * NH + gn0 + nq;
            *(float4*)op = make_float4(hn[0], hn[1], hn[2], hn[3]);
            *(float4*)(op + 4) = make_float4(hn[4], hn[5], hn[6], hn[7]);
            __syncthreads();
            pack_planes(sbuf, g_hhf[(t + 1) & 1], g_hlf[(t + 1) & 1], j * 2, tid);
            __syncthreads();
            if (tid == 0) { __threadfence(); st_rel(&g_fh[j], t + 1); }
        }
        if (write_last) {
            float* op = out + (size_t)TSTEPS * BATCH * NH + (size_t)m * NH + gn0 + nq;
            *(float4*)op = make_float4(hreg[0], hreg[1], hreg[2], hreg[3]);
            *(float4*)(op + 4) = make_float4(hreg[4], hreg[5], hreg[6], hreg[7]);
        }
    }
}

// ============================= launch =======================================
extern "C" void kernel_launch(void* const* d_in, const int* in_sizes, int n_in,
                              void* d_out, int out_size)
{
    const float* input = (const float*)d_in[0];
    const float* h0    = (const float*)d_in[1];
    const float* Wiz_w = (const float*)d_in[2];
    const float* Wiz_b = (const float*)d_in[3];
    const float* Wir_w = (const float*)d_in[4];
    const float* Wir_b = (const float*)d_in[5];
    const float* Wih_w = (const float*)d_in[6];
    const float* Wih_b = (const float*)d_in[7];
    const float* Whz_w = (const float*)d_in[8];
    const float* Whz_b = (const float*)d_in[9];
    const float* Whr_w = (const float*)d_in[10];
    const float* Whr_b = (const float*)d_in[11];
    const float* Whh_w = (const float*)d_in[12];
    const float* Whh_b = (const float*)d_in[13];
    const void*  lengths = d_in[14];

    cudaFuncSetAttribute(input_proj_kernel,
                         cudaFuncAttributeMaxDynamicSharedMemorySize, PA_SMEM);
    cudaFuncSetAttribute(gru_step_kernel,
                         cudaFuncAttributeMaxDynamicSharedMemorySize, PB_SMEM);

    init_misc_kernel<<<1, 32>>>();
    input_proj_kernel<<<256 * 24, 256, PA_SMEM>>>(input, Wiz_w, Wir_w, Wih_w);

    int write_last = (out_size >= TSTEPS * BATCH * NH + BATCH * NH) ? 1 : 0;
    gru_step_kernel<<<NBLK, 256, PB_SMEM>>>(
        h0, Whz_w, Whr_w, Whh_w, Whz_b, Whr_b, Whh_b,
        Wiz_b, Wir_b, Wih_b, lengths, (float*)d_out, write_last);
}

// round 8
// speedup vs baseline: 1.3657x; 1.1048x over previous
#include <cuda_runtime.h>
#include <cuda_bf16.h>
#include <cstdint>
#include <math.h>

#define TSTEPS 512
#define BATCH  64
#define NIN    512
#define NH     1024
#define NBLK   128

// ============================ global scratch ================================
__device__ float g_X[(size_t)3 * TSTEPS * BATCH * NH];   // input projections
__device__ float g_h32[BATCH * NH];                      // h (fp32, plain)
// A-operand planes in mma fragment order: frag(kf,mf)=kf*4+mf -> uint4[frag*32+lane]
__device__ uint4 g_hhf[2][8192], g_hlf[2][8192];         // h split planes (parity)
__device__ uint4 g_rhhf[8192], g_rhlf[8192];             // r*h split planes
__device__ float g_cpart[64 * 64 * 16];                  // c-gemm low-K partials
__device__ int g_fh[64], g_frh[64], g_fcp[64];           // step flags

// ============================ helpers =======================================
__device__ __forceinline__ uint32_t bfpack(float x, float y) {
    __nv_bfloat162 t = __floats2bfloat162_rn(x, y);
    return *(uint32_t*)&t;
}
__device__ __forceinline__ void splitp(float x, float y, uint32_t& hi, uint32_t& lo) {
    float hx = __bfloat162float(__float2bfloat16(x));
    float hy = __bfloat162float(__float2bfloat16(y));
    hi = bfpack(hx, hy);
    lo = bfpack(x - hx, y - hy);
}
__device__ __forceinline__ void mma16816(float* c, const uint32_t* a, const uint32_t* b) {
    asm volatile("mma.sync.aligned.m16n8k16.row.col.f32.bf16.bf16.f32 "
        "{%0,%1,%2,%3},{%4,%5,%6,%7},{%8,%9},{%0,%1,%2,%3};"
        : "+f"(c[0]), "+f"(c[1]), "+f"(c[2]), "+f"(c[3])
        : "r"(a[0]), "r"(a[1]), "r"(a[2]), "r"(a[3]), "r"(b[0]), "r"(b[1]));
}
__device__ __forceinline__ int ld_acq(const int* p) {
    int v;
    asm volatile("ld.acquire.gpu.global.s32 %0, [%1];" : "=r"(v) : "l"(p) : "memory");
    return v;
}
__device__ __forceinline__ void st_rel(int* p, int v) {
    asm volatile("st.release.gpu.global.s32 [%0], %1;" :: "l"(p), "r"(v) : "memory");
}
// single-warp polling (warp 0), block released by syncthreads
__device__ __forceinline__ void block_wait64(const int* flags, int target) {
    if (threadIdx.x < 32) {
        const int* p0 = flags + threadIdx.x;
        const int* p1 = flags + 32 + threadIdx.x;
        while (!__all_sync(0xFFFFFFFFu,
                           (ld_acq(p0) >= target) && (ld_acq(p1) >= target)))
            __nanosleep(60);
    }
    __syncthreads();
}
__device__ __forceinline__ void block_wait32(const int* flags, int target) {
    if (threadIdx.x < 32) {
        while (!__all_sync(0xFFFFFFFFu, ld_acq(flags + threadIdx.x) >= target))
            __nanosleep(60);
    }
    __syncthreads();
}
__device__ __forceinline__ void block_wait1(const int* flag, int target) {
    if (threadIdx.x == 0) {
        while (ld_acq(flag) < target) __nanosleep(60);
    }
    __syncthreads();
}

// =================== init: reset flags each launch ==========================
__global__ void init_misc_kernel() {
    int i = threadIdx.x;
    if (i < 64) { g_fh[i] = -1; g_frh[i] = -1; g_fcp[i] = -1; }
}

// ======================= phase A: input projections =========================
#define PA_AH 0
#define PA_AL 32768
#define PA_WH 65536
#define PA_WL 98304
#define PA_SMEM 131072

__global__ void __launch_bounds__(256) input_proj_kernel(
    const float* __restrict__ input,
    const float* __restrict__ Wiz, const float* __restrict__ Wir,
    const float* __restrict__ Wih)
{
    extern __shared__ char sm[];
    uint4* Ah = (uint4*)(sm + PA_AH);
    uint4* Al = (uint4*)(sm + PA_AL);
    uint2* Wh = (uint2*)(sm + PA_WH);
    uint2* Wl = (uint2*)(sm + PA_WL);
    const int tid = threadIdx.x, wid = tid >> 5, lane = tid & 31;
    const int ntile = blockIdx.x % 24, mtile = blockIdx.x / 24;
    const int gate = ntile >> 3, n0g = (ntile & 7) * 128, m0 = mtile * 128;
    const float* W = (gate == 0) ? Wiz : ((gate == 1) ? Wir : Wih);
    const int mg = wid & 3, ng = wid >> 2;

    float c[2][8][4];
#pragma unroll
    for (int i = 0; i < 2; i++)
#pragma unroll
        for (int j = 0; j < 8; j++)
#pragma unroll
            for (int k = 0; k < 4; k++) c[i][j][k] = 0.0f;

    for (int ch = 0; ch < 4; ch++) {
        const int k0 = ch * 128;
        __syncthreads();
#pragma unroll
        for (int it = 0; it < 8; it++) {
            int idx = tid + (it << 8);
            int frag = idx >> 5, l = idx & 31;
            int kf = frag >> 3, mf = frag & 7;
            int r = l >> 2, c2 = (l & 3) * 2;
            const float* src = input + (size_t)(m0 + mf * 16 + r) * NIN + k0 + kf * 16 + c2;
            float2 p0 = *(const float2*)(src);
            float2 p1 = *(const float2*)(src + 8 * NIN);
            float2 p2 = *(const float2*)(src + 8);
            float2 p3 = *(const float2*)(src + 8 * NIN + 8);
            uint32_t h0, h1, h2, h3, lo0, lo1, lo2, lo3;
            splitp(p0.x, p0.y, h0, lo0); splitp(p1.x, p1.y, h1, lo1);
            splitp(p2.x, p2.y, h2, lo2); splitp(p3.x, p3.y, h3, lo3);
            Ah[frag * 32 + l] = make_uint4(h0, h1, h2, h3);
            Al[frag * 32 + l] = make_uint4(lo0, lo1, lo2, lo3);
        }
#pragma unroll
        for (int it = 0; it < 16; it++) {
            int idx = tid + (it << 8);
            int frag = idx >> 5, l = idx & 31;
            int kf = frag >> 4, nf = frag & 15;
            int n = nf * 8 + (l >> 2), k = kf * 16 + (l & 3) * 2;
            const float* src = W + (size_t)(n0g + n) * NIN + k0 + k;
            float2 q0 = *(const float2*)src;
            float2 q1 = *(const float2*)(src + 8);
            uint32_t h0, h1, lo0, lo1;
            splitp(q0.x, q0.y, h0, lo0); splitp(q1.x, q1.y, h1, lo1);
            Wh[frag * 32 + l] = make_uint2(h0, h1);
            Wl[frag * 32 + l] = make_uint2(lo0, lo1);
        }
        __syncthreads();
#pragma unroll 2
        for (int s = 0; s < 8; s++) {
            uint4 ah[2], al[2];
            uint2 bh[8], bl[8];
            ah[0] = Ah[(s * 8 + mg * 2 + 0) * 32 + lane];
            ah[1] = Ah[(s * 8 + mg * 2 + 1) * 32 + lane];
            al[0] = Al[(s * 8 + mg * 2 + 0) * 32 + lane];
            al[1] = Al[(s * 8 + mg * 2 + 1) * 32 + lane];
#pragma unroll
            for (int nf = 0; nf < 8; nf++) {
                bh[nf] = Wh[(s * 16 + ng * 8 + nf) * 32 + lane];
                bl[nf] = Wl[(s * 16 + ng * 8 + nf) * 32 + lane];
            }
#pragma unroll
            for (int mf = 0; mf < 2; mf++)
#pragma unroll
                for (int nf = 0; nf < 8; nf++) {
                    mma16816(c[mf][nf], &ah[mf].x, &bh[nf].x);
                    mma16816(c[mf][nf], &al[mf].x, &bh[nf].x);
                    mma16816(c[mf][nf], &ah[mf].x, &bl[nf].x);
                }
        }
    }
    const int r = lane >> 2, c2 = (lane & 3) * 2;
#pragma unroll
    for (int mf = 0; mf < 2; mf++)
#pragma unroll
        for (int nf = 0; nf < 8; nf++) {
            size_t row = (size_t)(m0 + (mg * 2 + mf) * 16 + r);
            size_t base = ((size_t)gate * TSTEPS * BATCH + row) * NH
                        + n0g + (ng * 8 + nf) * 8 + c2;
            *(float2*)(g_X + base) = make_float2(c[mf][nf][0], c[mf][nf][1]);
            *(float2*)(g_X + base + (size_t)8 * NH) = make_float2(c[mf][nf][2], c[mf][nf][3]);
        }
}

// ======================= phase B: persistent GRU ============================
// 128 blocks. 0-63 "zc": z-gate (16 cols) + c high-K half + h update.
// 64-127 "rc": r-gate (16 cols) + c low-K half (partials to paired zc block).
#define W1_H 0          // gate W hi (128 frags)   32768
#define W1_L 32768
#define W2_H 65536      // c-half W hi (64 frags)  16384
#define W2_L 81920
#define PB_SCR  98304   // float[4][64][20]        20480
#define PB_SBUF 118784  // float[64][20]            5120
#define PB_BIA  123904  // float[32]  (biaG | biaC)
#define PB_SLEN 124032  // int[64]
#define PB_SMEM 124416

// C[64 x 16] += A[64 x 16*KF*4] @ W^T, 3-term, depth-2 operand pipeline.
template<int KF>
__device__ __forceinline__ void gemm_t(const uint4* __restrict__ Aph,
                                       const uint4* __restrict__ Apl,
                                       int akf0,
                                       const uint2* __restrict__ Wh,
                                       const uint2* __restrict__ Wl,
                                       float* __restrict__ scr,
                                       int wid, int lane)
{
    const int mg = wid & 1, kg = wid >> 1;
    const int kfl0 = kg * KF;
    float c[2][2][4];
#pragma unroll
    for (int i = 0; i < 2; i++)
#pragma unroll
        for (int j = 0; j < 2; j++)
#pragma unroll
            for (int k = 0; k < 4; k++) c[i][j][k] = 0.0f;

    uint4 ah[2][2], al[2][2];
    uint2 bh[2][2], bl[2][2];
    {
        int af = ((akf0 + kfl0) * 4 + mg * 2) * 32 + lane;
        ah[0][0] = Aph[af]; ah[0][1] = Aph[af + 32];
        al[0][0] = Apl[af]; al[0][1] = Apl[af + 32];
        int wf = (kfl0 * 2) * 32 + lane;
        bh[0][0] = Wh[wf]; bh[0][1] = Wh[wf + 32];
        bl[0][0] = Wl[wf]; bl[0][1] = Wl[wf + 32];
    }
#pragma unroll
    for (int s = 0; s < KF; s++) {
        const int cur = s & 1, nxt = cur ^ 1;
        if (s + 1 < KF) {
            int af = ((akf0 + kfl0 + s + 1) * 4 + mg * 2) * 32 + lane;
            ah[nxt][0] = Aph[af]; ah[nxt][1] = Aph[af + 32];
            al[nxt][0] = Apl[af]; al[nxt][1] = Apl[af + 32];
            int wf = ((kfl0 + s + 1) * 2) * 32 + lane;
            bh[nxt][0] = Wh[wf]; bh[nxt][1] = Wh[wf + 32];
            bl[nxt][0] = Wl[wf]; bl[nxt][1] = Wl[wf + 32];
        }
#pragma unroll
        for (int mf = 0; mf < 2; mf++)
#pragma unroll
            for (int nf = 0; nf < 2; nf++) {
                mma16816(c[mf][nf], &ah[cur][mf].x, &bh[cur][nf].x);
                mma16816(c[mf][nf], &al[cur][mf].x, &bh[cur][nf].x);
                mma16816(c[mf][nf], &ah[cur][mf].x, &bl[cur][nf].x);
            }
    }
    const int r = lane >> 2, c2 = (lane & 3) * 2;
#pragma unroll
    for (int mf = 0; mf < 2; mf++)
#pragma unroll
        for (int nf = 0; nf < 2; nf++) {
            float* p = scr + (kg * 64 + mg * 32 + mf * 16 + r) * 20 + nf * 8 + c2;
            *(float2*)p = make_float2(c[mf][nf][0], c[mf][nf][1]);
            *(float2*)(p + 8 * 20) = make_float2(c[mf][nf][2], c[mf][nf][3]);
        }
}

__device__ __forceinline__ void reduce4(const float* __restrict__ scr,
                                        int m, int nq, float* pre)
{
#pragma unroll
    for (int kg = 0; kg < 4; kg++) {
        float4 a = *(const float4*)(scr + kg * 1280 + m * 20 + nq);
        pre[0] += a.x; pre[1] += a.y; pre[2] += a.z; pre[3] += a.w;
    }
}

// pack sbuf[64][20] (16 cols of values) into A-frag planes at kf = jkf
__device__ __forceinline__ void pack16(const float* __restrict__ sbuf,
                                       uint4* __restrict__ dsth,
                                       uint4* __restrict__ dstl,
                                       int jkf, int wid, int lane)
{
    if (wid < 4) {
        const int mf = wid;
        const int r = lane >> 2, c2 = (lane & 3) * 2;
        const float* p = sbuf + (mf * 16 + r) * 20 + c2;
        uint32_t h0, h1, h2, h3, l0, l1, l2, l3;
        splitp(p[0], p[1], h0, l0);
        splitp(p[160], p[161], h1, l1);
        splitp(p[8], p[9], h2, l2);
        splitp(p[168], p[169], h3, l3);
        const int fi = (jkf * 4 + mf) * 32 + lane;
        dsth[fi] = make_uint4(h0, h1, h2, h3);
        dstl[fi] = make_uint4(l0, l1, l2, l3);
    }
}

__global__ void __launch_bounds__(256, 1) gru_step_kernel(
    const float* __restrict__ h0in,
    const float* __restrict__ Whz, const float* __restrict__ Whr,
    const float* __restrict__ Whh,
    const float* __restrict__ Whz_b, const float* __restrict__ Whr_b,
    const float* __restrict__ Whh_b,
    const float* __restrict__ Wiz_b, const float* __restrict__ Wir_b,
    const float* __restrict__ Wih_b,
    const void* __restrict__ lengths,
    float* __restrict__ out, int write_last)
{
    extern __shared__ char sm[];
    uint2* W1h = (uint2*)(sm + W1_H);
    uint2* W1l = (uint2*)(sm + W1_L);
    uint2* W2h = (uint2*)(sm + W2_H);
    uint2* W2l = (uint2*)(sm + W2_L);
    float* scr = (float*)(sm + PB_SCR);
    float* sbuf = (float*)(sm + PB_SBUF);
    float* bia = (float*)(sm + PB_BIA);     // [0:16) gate, [16:32) cand
    int* slen = (int*)(sm + PB_SLEN);

    const int tid = threadIdx.x, wid = tid >> 5, lane = tid & 31;
    const int b = blockIdx.x;
    const int is_zc = (b < 64);
    const int j = b & 63;
    const int gn0 = j * 16;

    const float* Wgate = is_zc ? Whz : Whr;
    const float* bgh   = is_zc ? Whz_b : Whr_b;
    const float* bgi   = is_zc ? Wiz_b : Wir_b;
    const int koff = is_zc ? 512 : 0;   // c-half K offset

    // ---- pack gate W slice (16 cols x K1024) : 128 frags ----
#pragma unroll 4
    for (int it = 0; it < 16; it++) {
        int idx = tid + (it << 8);
        int frag = idx >> 5, l = idx & 31;
        int kf = frag >> 1, nf = frag & 1;
        int n = nf * 8 + (l >> 2), k = kf * 16 + (l & 3) * 2;
        const float* src = Wgate + (size_t)(gn0 + n) * NH + k;
        float2 q0 = *(const float2*)src;
        float2 q1 = *(const float2*)(src + 8);
        uint32_t h0, h1, lo0, lo1;
        splitp(q0.x, q0.y, h0, lo0); splitp(q1.x, q1.y, h1, lo1);
        W1h[frag * 32 + l] = make_uint2(h0, h1);
        W1l[frag * 32 + l] = make_uint2(lo0, lo1);
    }
    // ---- pack c-half W slice (16 cols x K512) : 64 frags ----
#pragma unroll 4
    for (int it = 0; it < 8; it++) {
        int idx = tid + (it << 8);
        int frag = idx >> 5, l = idx & 31;
        int kf = frag >> 1, nf = frag & 1;
        int n = nf * 8 + (l >> 2), k = koff + kf * 16 + (l & 3) * 2;
        const float* src = Whh + (size_t)(gn0 + n) * NH + k;
        float2 q0 = *(const float2*)src;
        float2 q1 = *(const float2*)(src + 8);
        uint32_t h0, h1, lo0, lo1;
        splitp(q0.x, q0.y, h0, lo0); splitp(q1.x, q1.y, h1, lo1);
        W2h[frag * 32 + l] = make_uint2(h0, h1);
        W2l[frag * 32 + l] = make_uint2(lo0, lo1);
    }
    if (tid < 16) {
        bia[tid] = bgh[gn0 + tid] + bgi[gn0 + tid];
        bia[16 + tid] = Whh_b[gn0 + tid] + Wih_b[gn0 + tid];
    }
    {   // lengths dtype auto-detect (int64 -> high word of elem0 is 0)
        const int* L32 = (const int*)lengths;
        int is64 = (L32[1] == 0);
        if (tid < BATCH)
            slen[tid] = is64 ? (int)((const long long*)lengths)[tid] : L32[tid];
    }

    const int m = tid >> 2, nq = (tid & 3) * 4;
    float hreg[4];

    if (is_zc) {
        // init h: registers + plain fp32 + frag planes parity 0
        const float* src = h0in + (size_t)m * NH + gn0 + nq;
        float4 v = *(const float4*)src;
        hreg[0] = v.x; hreg[1] = v.y; hreg[2] = v.z; hreg[3] = v.w;
        *(float4*)(g_h32 + (size_t)m * NH + gn0 + nq) = v;
        *(float4*)(sbuf + m * 20 + nq) = v;
        __syncthreads();
        pack16(sbuf, g_hhf[0], g_hlf[0], j, wid, lane);
        __syncthreads();
        if (tid == 0) { __threadfence(); st_rel(&g_fh[j], 0); }
    } else {
        __syncthreads();
    }

    const int sl = slen[m];
    const size_t GATE = (size_t)TSTEPS * BATCH * NH;
    const size_t xrow = (size_t)m * NH + gn0 + nq;

    if (is_zc) {
        const float* Xz = g_X + xrow;               // gate 0
        const float* Xh = g_X + 2 * GATE + xrow;    // gate 2
        float* cpart = g_cpart + j * 1024 + m * 16 + nq;
        for (int t = 0; t < TSTEPS; t++) {
            float4 xz = *(const float4*)(Xz + (size_t)t * BATCH * NH);
            float4 xh = *(const float4*)(Xh + (size_t)t * BATCH * NH);
            // ---- z gemm ----
            block_wait64(g_fh, t);
            gemm_t<16>(g_hhf[t & 1], g_hlf[t & 1], 0, W1h, W1l, scr, wid, lane);
            __syncthreads();
            float zv[4] = {xz.x + bia[nq], xz.y + bia[nq + 1],
                           xz.z + bia[nq + 2], xz.w + bia[nq + 3]};
            reduce4(scr, m, nq, zv);
#pragma unroll
            for (int jj = 0; jj < 4; jj++) zv[jj] = 1.0f / (1.0f + expf(-zv[jj]));
            // ---- c gemm, high K half (wait also closes scr-consume window) ----
            block_wait32(g_frh + 32, t + 1);
            gemm_t<8>(g_rhhf, g_rhlf, 32, W2h, W2l, scr, wid, lane);
            __syncthreads();
            // ---- merge with partner's low-K partial, finish step ----
            block_wait1(&g_fcp[j], t + 1);
            float4 cp = *(const float4*)cpart;
            float pre[4] = {xh.x + bia[16 + nq] + cp.x, xh.y + bia[16 + nq + 1] + cp.y,
                            xh.z + bia[16 + nq + 2] + cp.z, xh.w + bia[16 + nq + 3] + cp.w};
            reduce4(scr, m, nq, pre);
            float hn[4];
#pragma unroll
            for (int jj = 0; jj < 4; jj++) {
                float hc = tanhf(pre[jj]);
                float v = (1.0f - zv[jj]) * hreg[jj] + zv[jj] * hc;
                if (t >= sl) v = hreg[jj];
                hreg[jj] = v;
                hn[jj] = v;
            }
            float4 hv = make_float4(hn[0], hn[1], hn[2], hn[3]);
            *(float4*)(g_h32 + (size_t)m * NH + gn0 + nq) = hv;
            *(float4*)(out + (size_t)t * BATCH * NH + xrow) = hv;
            *(float4*)(sbuf + m * 20 + nq) = hv;
            __syncthreads();
            pack16(sbuf, g_hhf[(t + 1) & 1], g_hlf[(t + 1) & 1], j, wid, lane);
            __syncthreads();
            if (tid == 0) { __threadfence(); st_rel(&g_fh[j], t + 1); }
        }
        if (write_last) {
            *(float4*)(out + (size_t)TSTEPS * BATCH * NH + xrow) =
                make_float4(hreg[0], hreg[1], hreg[2], hreg[3]);
        }
    } else {
        const float* Xr = g_X + GATE + xrow;        // gate 1
        float* cpart = g_cpart + j * 1024 + m * 16 + nq;
        for (int t = 0; t < TSTEPS; t++) {
            float4 xr = *(const float4*)(Xr + (size_t)t * BATCH * NH);
            // ---- r gemm ----
            block_wait64(g_fh, t);
            gemm_t<16>(g_hhf[t & 1], g_hlf[t & 1], 0, W1h, W1l, scr, wid, lane);
            __syncthreads();
            float pre[4] = {xr.x + bia[nq], xr.y + bia[nq + 1],
                            xr.z + bia[nq + 2], xr.w + bia[nq + 3]};
            reduce4(scr, m, nq, pre);
            float4 hp = *(const float4*)(g_h32 + (size_t)m * NH + gn0 + nq);
            float hv[4] = {hp.x, hp.y, hp.z, hp.w};
            float rh[4];
#pragma unroll
            for (int jj = 0; jj < 4; jj++) {
                float s = 1.0f / (1.0f + expf(-pre[jj]));
                rh[jj] = s * hv[jj];
            }
            *(float4*)(sbuf + m * 20 + nq) = make_float4(rh[0], rh[1], rh[2], rh[3]);
            __syncthreads();
            pack16(sbuf, g_rhhf, g_rhlf, j, wid, lane);
            __syncthreads();
            if (tid == 0) { __threadfence(); st_rel(&g_frh[j], t + 1); }
            // ---- c gemm, low K half ----
            block_wait32(g_frh, t + 1);
            gemm_t<8>(g_rhhf, g_rhlf, 0, W2h, W2l, scr, wid, lane);
            __syncthreads();
            float part[4] = {0.0f, 0.0f, 0.0f, 0.0f};
            reduce4(scr, m, nq, part);
            *(float4*)cpart = make_float4(part[0], part[1], part[2], part[3]);
            __syncthreads();
            if (tid == 0) { __threadfence(); st_rel(&g_fcp[j], t + 1); }
        }
    }
}

// ============================= launch =======================================
extern "C" void kernel_launch(void* const* d_in, const int* in_sizes, int n_in,
                              void* d_out, int out_size)
{
    const float* input = (const float*)d_in[0];
    const float* h0    = (const float*)d_in[1];
    const float* Wiz_w = (const float*)d_in[2];
    const float* Wiz_b = (const float*)d_in[3];
    const float* Wir_w = (const float*)d_in[4];
    const float* Wir_b = (const float*)d_in[5];
    const float* Wih_w = (const float*)d_in[6];
    const float* Wih_b = (const float*)d_in[7];
    const float* Whz_w = (const float*)d_in[8];
    const float* Whz_b = (const float*)d_in[9];
    const float* Whr_w = (const float*)d_in[10];
    const float* Whr_b = (const float*)d_in[11];
    const float* Whh_w = (const float*)d_in[12];
    const float* Whh_b = (const float*)d_in[13];
    const void*  lengths = d_in[14];

    cudaFuncSetAttribute(input_proj_kernel,
                         cudaFuncAttributeMaxDynamicSharedMemorySize, PA_SMEM);
    cudaFuncSetAttribute(gru_step_kernel,
                         cudaFuncAttributeMaxDynamicSharedMemorySize, PB_SMEM);

    init_misc_kernel<<<1, 64>>>();
    input_proj_kernel<<<256 * 24, 256, PA_SMEM>>>(input, Wiz_w, Wir_w, Wih_w);

    int write_last = (out_size >= TSTEPS * BATCH * NH + BATCH * NH) ? 1 : 0;
    gru_step_kernel<<<NBLK, 256, PB_SMEM>>>(
        h0, Whz_w, Whr_w, Whh_w, Whz_b, Whr_b, Whh_b,
        Wiz_b, Wir_b, Wih_b, lengths, (float*)d_out, write_last);
}